// round 2
// baseline (speedup 1.0000x reference)
#include <cuda_runtime.h>
#include <cstdint>

#define NN   50000
#define EE   1600000
#define INC  128
#define OUTC 64

// Scratch (allocation-free contract: __device__ globals)
__device__ int   g_cnt[NN];
__device__ int   g_cur[NN];
__device__ int   g_off[NN + 1];
__device__ float g_dinv[NN];
__device__ __align__(16) float g_feat[(size_t)NN * OUTC];
__device__ int   g_src[EE];
__device__ int   g_is64;

// ---------------- dtype detect (int64 vs int32 edge_index) ----------------
__global__ void detect_k(const int* __restrict__ ei32) {
    __shared__ int zeros;
    if (threadIdx.x == 0) zeros = 0;
    __syncthreads();
    // odd 32-bit words: int64 high halves (always 0 for ids < 2^31) vs random ids
    int z = (ei32[2 * threadIdx.x + 1] == 0) ? 1 : 0;
    atomicAdd(&zeros, z);
    __syncthreads();
    if (threadIdx.x == 0) g_is64 = (zeros > 128) ? 1 : 0;
}

__device__ __forceinline__ int load_idx(const int* ei32, size_t pos) {
    if (g_is64) return (int)((const long long*)ei32)[pos];
    return ei32[pos];
}

// ---------------- zero counters ----------------
__global__ void zero_k(int n) {
    int i = blockIdx.x * blockDim.x + threadIdx.x;
    if (i < n) { g_cnt[i] = 0; g_cur[i] = 0; }
}

// ---------------- degree count (targets) ----------------
__global__ void count_k(const int* __restrict__ ei32, int E) {
    int e = blockIdx.x * blockDim.x + threadIdx.x;
    if (e >= E) return;
    int col = load_idx(ei32, (size_t)E + e);
    atomicAdd(&g_cnt[col], 1);
}

// ---------------- single-block scan + dinv ----------------
__global__ __launch_bounds__(1024) void scan_k(int n) {
    __shared__ int s[1024];
    int t = threadIdx.x;
    int chunk = (n + 1023) / 1024;
    int beg = t * chunk;
    int end = min(beg + chunk, n);
    int sum = 0;
    for (int i = beg; i < end; i++) sum += g_cnt[i];
    s[t] = sum;
    __syncthreads();
    // Hillis-Steele inclusive scan
    for (int d = 1; d < 1024; d <<= 1) {
        int v = (t >= d) ? s[t - d] : 0;
        __syncthreads();
        s[t] += v;
        __syncthreads();
    }
    int run = s[t] - sum;  // exclusive prefix
    for (int i = beg; i < end; i++) {
        int c = g_cnt[i];
        g_off[i] = run;
        run += c;
        g_dinv[i] = rsqrtf((float)(c + 1));  // +1 self-loop
    }
    if (t == 1023) g_off[n] = run;
}

// ---------------- CSR fill ----------------
__global__ void fill_k(const int* __restrict__ ei32, int E) {
    int e = blockIdx.x * blockDim.x + threadIdx.x;
    if (e >= E) return;
    int row = load_idx(ei32, (size_t)e);
    int col = load_idx(ei32, (size_t)E + e);
    int pos = g_off[col] + atomicAdd(&g_cur[col], 1);
    g_src[pos] = row;
}

// ---------------- fused linear + pre-scale: g_feat = (x@W)*dinv ----------------
__global__ __launch_bounds__(128) void gemm_k(
    const float* __restrict__ x, const float* __restrict__ W, int n)
{
    __shared__ float4 Ws[INC * (OUTC / 4)];  // [k][o4], 32 KB
    const float4* W4 = (const float4*)W;
    for (int i = threadIdx.x; i < INC * (OUTC / 4); i += 128) Ws[i] = W4[i];
    __syncthreads();

    int row = blockIdx.x * 128 + threadIdx.x;
    if (row >= n) return;

    float acc[OUTC];
#pragma unroll
    for (int o = 0; o < OUTC; o++) acc[o] = 0.f;

    const float4* xr = (const float4*)(x + (size_t)row * INC);
#pragma unroll 4
    for (int k4 = 0; k4 < INC / 4; k4++) {
        float4 xq = __ldg(xr + k4);
        float xv[4] = {xq.x, xq.y, xq.z, xq.w};
#pragma unroll
        for (int j = 0; j < 4; j++) {
            int k = k4 * 4 + j;
#pragma unroll
            for (int o4 = 0; o4 < OUTC / 4; o4++) {
                float4 w = Ws[k * (OUTC / 4) + o4];
                acc[o4 * 4 + 0] += xv[j] * w.x;
                acc[o4 * 4 + 1] += xv[j] * w.y;
                acc[o4 * 4 + 2] += xv[j] * w.z;
                acc[o4 * 4 + 3] += xv[j] * w.w;
            }
        }
    }

    float s = g_dinv[row];
    float4* gp = (float4*)(g_feat + (size_t)row * OUTC);
#pragma unroll
    for (int o4 = 0; o4 < OUTC / 4; o4++) {
        gp[o4] = make_float4(acc[o4 * 4 + 0] * s, acc[o4 * 4 + 1] * s,
                             acc[o4 * 4 + 2] * s, acc[o4 * 4 + 3] * s);
    }
}

// ---------------- warp-per-node gather + epilogue ----------------
// Lanes 0-15 handle even CSR entries, 16-31 odd; each lane owns one float4
// slice (p = lane&15). Halves combined by shfl.xor(16). Self-loop term is
// the initial accumulator of half 0.
__global__ __launch_bounds__(256) void gather_k(
    const float* __restrict__ b, float* __restrict__ out, int n)
{
    int warp = (blockIdx.x * blockDim.x + threadIdx.x) >> 5;
    if (warp >= n) return;
    int lane = threadIdx.x & 31;
    int half = lane >> 4;
    int p    = lane & 15;

    const float4* gf = (const float4*)g_feat;
    float4 acc = make_float4(0.f, 0.f, 0.f, 0.f);
    if (half == 0) acc = gf[(size_t)warp * (OUTC / 4) + p];  // self-loop

    int s0 = g_off[warp], s1 = g_off[warp + 1];
    for (int j = s0 + half; j < s1; j += 2) {
        int r = g_src[j];
        float4 v = __ldg(gf + (size_t)r * (OUTC / 4) + p);
        acc.x += v.x; acc.y += v.y; acc.z += v.z; acc.w += v.w;
    }

    acc.x += __shfl_xor_sync(0xffffffffu, acc.x, 16);
    acc.y += __shfl_xor_sync(0xffffffffu, acc.y, 16);
    acc.z += __shfl_xor_sync(0xffffffffu, acc.z, 16);
    acc.w += __shfl_xor_sync(0xffffffffu, acc.w, 16);

    if (half == 0) {
        float  s  = g_dinv[warp];
        float4 bq = __ldg((const float4*)b + p);
        float4 o;
        o.x = acc.x * s + bq.x;
        o.y = acc.y * s + bq.y;
        o.z = acc.z * s + bq.z;
        o.w = acc.w * s + bq.w;
        ((float4*)out)[(size_t)warp * (OUTC / 4) + p] = o;
    }
}

extern "C" void kernel_launch(void* const* d_in, const int* in_sizes, int n_in,
                              void* d_out, int out_size)
{
    const float* x    = (const float*)d_in[0];
    const int*   ei32 = (const int*)d_in[1];
    const float* W    = (const float*)d_in[2];
    const float* b    = (const float*)d_in[3];
    float* out = (float*)d_out;

    int n = in_sizes[0] / INC;   // 50000
    int E = in_sizes[1] / 2;     // 1600000 (element count is dtype-independent? see detect)

    detect_k<<<1, 256>>>(ei32);
    zero_k<<<(n + 255) / 256, 256>>>(n);
    count_k<<<(E + 255) / 256, 256>>>(ei32, E);
    scan_k<<<1, 1024>>>(n);
    gemm_k<<<(n + 127) / 128, 128>>>(x, W, n);
    fill_k<<<(E + 255) / 256, 256>>>(ei32, E);
    gather_k<<<(n * 32 + 255) / 256, 256>>>(b, out, n);
}

// round 4
// speedup vs baseline: 1.6269x; 1.6269x over previous
#include <cuda_runtime.h>
#include <cstdint>

#define NN   50000
#define EE   1600000
#define INC  128
#define OUTC 64
#define NB   ((NN + 255) / 256)   // 196 scan blocks

// Scratch (allocation-free contract: __device__ globals)
__device__ int   g_cnt[NN];
__device__ int   g_cur[NN];
__device__ int   g_off[NN + 1];
__device__ int   g_bsum[NB];
__device__ int   g_bpre[NB];
__device__ float g_dinv[NN];
__device__ __align__(16) float g_feat[(size_t)NN * OUTC];
__device__ int   g_src[EE];
__device__ int   g_is64;

// ---------------- dtype detect (int64 vs int32 edge_index) ----------------
__global__ void detect_k(const int* __restrict__ ei32) {
    __shared__ int zeros;
    if (threadIdx.x == 0) zeros = 0;
    __syncthreads();
    // odd 32-bit words: int64 high halves (always 0 for ids < 2^31) vs random ids
    int z = (ei32[2 * threadIdx.x + 1] == 0) ? 1 : 0;
    atomicAdd(&zeros, z);
    __syncthreads();
    if (threadIdx.x == 0) g_is64 = (zeros > 128) ? 1 : 0;
}

__device__ __forceinline__ int load_idx(const int* ei32, size_t pos) {
    if (g_is64) return (int)((const long long*)ei32)[pos];
    return ei32[pos];
}

// ---------------- zero counters ----------------
__global__ void zero_k(int n) {
    int i = blockIdx.x * blockDim.x + threadIdx.x;
    if (i < n) { g_cnt[i] = 0; g_cur[i] = 0; }
}

// ---------------- degree count (targets) ----------------
__global__ void count_k(const int* __restrict__ ei32, int E) {
    int e = blockIdx.x * blockDim.x + threadIdx.x;
    if (e >= E) return;
    int col = load_idx(ei32, (size_t)E + e);
    atomicAdd(&g_cnt[col], 1);
}

// ---------------- 3-phase scan ----------------
// Phase 1: per-block sum of 256 counts; ALSO writes g_dinv (depends only on
// g_cnt, final after count_k) so gemm_k can run before offs_k.
__global__ __launch_bounds__(256) void partial_k(int n) {
    __shared__ int s[256];
    int i = blockIdx.x * 256 + threadIdx.x;
    int c = (i < n) ? g_cnt[i] : 0;
    if (i < n) g_dinv[i] = rsqrtf((float)(c + 1));  // +1 self-loop
    s[threadIdx.x] = c;
    __syncthreads();
#pragma unroll
    for (int d = 128; d > 0; d >>= 1) {
        if (threadIdx.x < d) s[threadIdx.x] += s[threadIdx.x + d];
        __syncthreads();
    }
    if (threadIdx.x == 0) g_bsum[blockIdx.x] = s[0];
}

// Phase 2: single small block scans the 196 block sums
__global__ __launch_bounds__(256) void scanb_k(int n) {
    __shared__ int s[256];
    int t = threadIdx.x;
    int v = (t < NB) ? g_bsum[t] : 0;
    s[t] = v;
    __syncthreads();
#pragma unroll
    for (int d = 1; d < 256; d <<= 1) {
        int u = (t >= d) ? s[t - d] : 0;
        __syncthreads();
        s[t] += u;
        __syncthreads();
    }
    if (t < NB) g_bpre[t] = s[t] - v;     // exclusive prefix
    if (t == 255) g_off[n] = s[255];      // total
}

// Phase 3: per-block exclusive scan + block prefix -> offsets
__global__ __launch_bounds__(256) void offs_k(int n) {
    __shared__ int s[256];
    int t = threadIdx.x;
    int i = blockIdx.x * 256 + t;
    int c = (i < n) ? g_cnt[i] : 0;
    s[t] = c;
    __syncthreads();
#pragma unroll
    for (int d = 1; d < 256; d <<= 1) {
        int u = (t >= d) ? s[t - d] : 0;
        __syncthreads();
        s[t] += u;
        __syncthreads();
    }
    if (i < n) g_off[i] = g_bpre[blockIdx.x] + s[t] - c;   // exclusive
}

// ---------------- CSR fill ----------------
__global__ void fill_k(const int* __restrict__ ei32, int E) {
    int e = blockIdx.x * blockDim.x + threadIdx.x;
    if (e >= E) return;
    int row = load_idx(ei32, (size_t)e);
    int col = load_idx(ei32, (size_t)E + e);
    int pos = g_off[col] + atomicAdd(&g_cur[col], 1);
    g_src[pos] = row;
}

// ---------------- fused linear + pre-scale: g_feat = (x@W)*dinv ----------------
__global__ __launch_bounds__(128) void gemm_k(
    const float* __restrict__ x, const float* __restrict__ W, int n)
{
    __shared__ float4 Ws[INC * (OUTC / 4)];  // [k][o4], 32 KB
    const float4* W4 = (const float4*)W;
    for (int i = threadIdx.x; i < INC * (OUTC / 4); i += 128) Ws[i] = W4[i];
    __syncthreads();

    int row = blockIdx.x * 128 + threadIdx.x;
    if (row >= n) return;

    float acc[OUTC];
#pragma unroll
    for (int o = 0; o < OUTC; o++) acc[o] = 0.f;

    const float4* xr = (const float4*)(x + (size_t)row * INC);
#pragma unroll 4
    for (int k4 = 0; k4 < INC / 4; k4++) {
        float4 xq = __ldg(xr + k4);
        float xv[4] = {xq.x, xq.y, xq.z, xq.w};
#pragma unroll
        for (int j = 0; j < 4; j++) {
            int k = k4 * 4 + j;
#pragma unroll
            for (int o4 = 0; o4 < OUTC / 4; o4++) {
                float4 w = Ws[k * (OUTC / 4) + o4];
                acc[o4 * 4 + 0] += xv[j] * w.x;
                acc[o4 * 4 + 1] += xv[j] * w.y;
                acc[o4 * 4 + 2] += xv[j] * w.z;
                acc[o4 * 4 + 3] += xv[j] * w.w;
            }
        }
    }

    float s = g_dinv[row];
    float4* gp = (float4*)(g_feat + (size_t)row * OUTC);
#pragma unroll
    for (int o4 = 0; o4 < OUTC / 4; o4++) {
        gp[o4] = make_float4(acc[o4 * 4 + 0] * s, acc[o4 * 4 + 1] * s,
                             acc[o4 * 4 + 2] * s, acc[o4 * 4 + 3] * s);
    }
}

// ---------------- warp-per-node gather + epilogue ----------------
// Lanes 0-15 handle even CSR entries, 16-31 odd; each lane owns one float4
// slice (p = lane&15). Halves combined by shfl.xor(16). Self-loop term is
// the initial accumulator of half 0.
__global__ __launch_bounds__(256) void gather_k(
    const float* __restrict__ b, float* __restrict__ out, int n)
{
    int warp = (blockIdx.x * blockDim.x + threadIdx.x) >> 5;
    if (warp >= n) return;
    int lane = threadIdx.x & 31;
    int half = lane >> 4;
    int p    = lane & 15;

    const float4* gf = (const float4*)g_feat;
    float4 acc = make_float4(0.f, 0.f, 0.f, 0.f);
    if (half == 0) acc = gf[(size_t)warp * (OUTC / 4) + p];  // self-loop

    int s0 = g_off[warp], s1 = g_off[warp + 1];
    for (int j = s0 + half; j < s1; j += 2) {
        int r = g_src[j];
        float4 v = __ldg(gf + (size_t)r * (OUTC / 4) + p);
        acc.x += v.x; acc.y += v.y; acc.z += v.z; acc.w += v.w;
    }

    acc.x += __shfl_xor_sync(0xffffffffu, acc.x, 16);
    acc.y += __shfl_xor_sync(0xffffffffu, acc.y, 16);
    acc.z += __shfl_xor_sync(0xffffffffu, acc.z, 16);
    acc.w += __shfl_xor_sync(0xffffffffu, acc.w, 16);

    if (half == 0) {
        float  s  = g_dinv[warp];
        float4 bq = __ldg((const float4*)b + p);
        float4 o;
        o.x = acc.x * s + bq.x;
        o.y = acc.y * s + bq.y;
        o.z = acc.z * s + bq.z;
        o.w = acc.w * s + bq.w;
        ((float4*)out)[(size_t)warp * (OUTC / 4) + p] = o;
    }
}

extern "C" void kernel_launch(void* const* d_in, const int* in_sizes, int n_in,
                              void* d_out, int out_size)
{
    const float* x    = (const float*)d_in[0];
    const int*   ei32 = (const int*)d_in[1];
    const float* W    = (const float*)d_in[2];
    const float* b    = (const float*)d_in[3];
    float* out = (float*)d_out;

    int n = in_sizes[0] / INC;   // 50000
    int E = in_sizes[1] / 2;     // 1600000

    detect_k<<<1, 256>>>(ei32);
    zero_k<<<(n + 255) / 256, 256>>>(n);
    count_k<<<(E + 255) / 256, 256>>>(ei32, E);
    partial_k<<<NB, 256>>>(n);    // also writes g_dinv
    scanb_k<<<1, 256>>>(n);
    gemm_k<<<(n + 127) / 128, 128>>>(x, W, n);   // needs g_dinv only
    offs_k<<<NB, 256>>>(n);
    fill_k<<<(E + 255) / 256, 256>>>(ei32, E);
    gather_k<<<(n * 32 + 255) / 256, 256>>>(b, out, n);
}